// round 4
// baseline (speedup 1.0000x reference)
#include <cuda_runtime.h>

// ---------------------------------------------------------------------------
// GCN(D=256) x2 + MLP head, algebraically folded:
//   out = A( A (X Wfold) + c1*1 ) + bc ,  Wfold = W1^T W2^T Wm1^T Wm2^T [256x5]
// A = D^{-1/2}(Adj+I)D^{-1/2}; dinv factored out; self-loop handled in epilogue.
// R4: CSR bucket-sort edges by dst once (hist/scan/scatter), then both
//     aggregation passes are atomic-free warp-per-node gathers with the
//     layer finalize math fused into the gather epilogue.
// ---------------------------------------------------------------------------

#define Dd 256
#define Hh 128
#define Cc 5
#define Ss 8              // padded row stride (32B rows -> 1 L2 sector)
#define NMAX 100352
#define EMAX 3276800

__device__ int   g_cnt[NMAX];        // in-degree (edges only, no self-loop)
__device__ int   g_rowstart[NMAX];   // CSR row starts (exclusive scan of cnt)
__device__ int   g_off[NMAX];        // running scatter offsets (starts = rowstart)
__device__ int   g_bsum[128];        // per-block partial sums for scan
__device__ int   g_srcs[EMAX];       // src indices bucketed by dst
__device__ float g_dinv[NMAX];       // 1/sqrt(deg+1)
__device__ float g_bufA[NMAX * Ss];  // z' = dinv*z
__device__ float g_bufB[NMAX * Ss];  // q  = dinv*p'
__device__ float g_M1[Dd * Cc];      // fold stage-1 intermediate
__device__ float g_WcT[Dd * Cc];     // fold stage-2 intermediate
__device__ float g_W[Dd * Cc];       // folded 256x5 weight
__device__ float g_c1[Cc];
__device__ float g_bc[Cc];

__global__ void init_kernel(int n) {
    int i = blockIdx.x * blockDim.x + threadIdx.x;
    if (i < n) g_cnt[i] = 0;
    if (i < Dd * Cc) { g_M1[i] = 0.f; g_WcT[i] = 0.f; g_W[i] = 0.f; }
}

__global__ void hist_kernel(const int* __restrict__ dst, int E) {
    int e = blockIdx.x * blockDim.x + threadIdx.x;
    if (e < E) atomicAdd(&g_cnt[__ldg(dst + e)], 1);
}

// scan1: per-block (1024 elems) sums -> g_bsum
__global__ void scan1_kernel(int n) {
    __shared__ int sh[256];
    int base = blockIdx.x * 1024;
    int t = threadIdx.x;
    int s = 0;
    #pragma unroll
    for (int j = 0; j < 4; ++j) {
        int i = base + t * 4 + j;
        if (i < n) s += g_cnt[i];
    }
    sh[t] = s; __syncthreads();
    for (int o = 128; o; o >>= 1) { if (t < o) sh[t] += sh[t + o]; __syncthreads(); }
    if (t == 0) g_bsum[blockIdx.x] = sh[0];
}

// scan2: single-block exclusive scan of block sums (nb <= 128)
__global__ void scan2_kernel(int nb) {
    __shared__ int sh[128];
    int t = threadIdx.x;
    int my = (t < nb) ? g_bsum[t] : 0;
    sh[t] = my; __syncthreads();
    for (int o = 1; o < 128; o <<= 1) {
        int v = (t >= o) ? sh[t - o] : 0;
        __syncthreads();
        sh[t] += v;
        __syncthreads();
    }
    if (t < nb) g_bsum[t] = sh[t] - my;  // exclusive
}

// scan3: full exclusive scan -> rowstart/off ; dinv from counts
__global__ void scan3_kernel(int n) {
    __shared__ int sh[256];
    int base = blockIdx.x * 1024;
    int t = threadIdx.x;
    int c[4]; int s = 0;
    #pragma unroll
    for (int j = 0; j < 4; ++j) {
        int i = base + t * 4 + j;
        c[j] = (i < n) ? g_cnt[i] : 0;
        s += c[j];
    }
    int my = s;
    sh[t] = s; __syncthreads();
    for (int o = 1; o < 256; o <<= 1) {
        int v = (t >= o) ? sh[t - o] : 0;
        __syncthreads();
        sh[t] += v;
        __syncthreads();
    }
    int run = g_bsum[blockIdx.x] + sh[t] - my;
    #pragma unroll
    for (int j = 0; j < 4; ++j) {
        int i = base + t * 4 + j;
        if (i < n) {
            g_rowstart[i] = run;
            g_off[i] = run;
            g_dinv[i] = rsqrtf((float)(c[j] + 1));  // +1 self-loop
            run += c[j];
        }
    }
}

__global__ void scatter_kernel(const int* __restrict__ src, const int* __restrict__ dst, int E) {
    int e = blockIdx.x * blockDim.x + threadIdx.x;
    if (e >= E) return;
    int d = __ldg(dst + e);
    int slot = atomicAdd(&g_off[d], 1);
    g_srcs[slot] = __ldg(src + e);
}

// Fold stage: Out[t][c] += sum_{k chunk} A[k*Dd + t] * B[k][c]; bT: B stored [Cc x kdim]
__global__ void stage_kernel(const float* __restrict__ A, const float* __restrict__ B,
                             float* __restrict__ Out, int kdim, int bT) {
    __shared__ float sB[Dd * Cc];
    int tid = threadIdx.x;
    for (int i = tid; i < kdim * Cc; i += blockDim.x) {
        int k = i / Cc, c = i - k * Cc;
        sB[i] = bT ? B[c * kdim + k] : B[i];
    }
    __syncthreads();
    int chunk = kdim / gridDim.x;
    int k0 = blockIdx.x * chunk;
    float acc[Cc] = {};
    for (int k = k0; k < k0 + chunk; ++k) {
        float a = A[k * Dd + tid];
        #pragma unroll
        for (int c = 0; c < Cc; ++c) acc[c] += a * sB[k * Cc + c];
    }
    #pragma unroll
    for (int c = 0; c < Cc; ++c) atomicAdd(&Out[tid * Cc + c], acc[c]);
}

// Bias folds: c1 = b1 @ WcT ; bc = Wm2 (Wm1 b2 + bm1) + bm2
__global__ void bias_kernel(const float* __restrict__ b1, const float* __restrict__ b2,
                            const float* __restrict__ Wm1, const float* __restrict__ bm1,
                            const float* __restrict__ Wm2, const float* __restrict__ bm2) {
    __shared__ float st[Hh];
    int tid = threadIdx.x, w = tid >> 5, lane = tid & 31;  // 8 warps
    for (int i = 0; i < 16; ++i) {
        int h = w * 16 + i;
        float s = 0.f;
        for (int d = lane; d < Dd; d += 32) s += Wm1[h * Dd + d] * b2[d];
        #pragma unroll
        for (int off = 16; off; off >>= 1) s += __shfl_xor_sync(0xFFFFFFFFu, s, off);
        if (lane == 0) st[h] = s + bm1[h];
    }
    __syncthreads();
    if (w < Cc) {
        float s1 = 0.f;
        for (int d = lane; d < Dd; d += 32) s1 += b1[d] * g_WcT[d * Cc + w];
        #pragma unroll
        for (int off = 16; off; off >>= 1) s1 += __shfl_xor_sync(0xFFFFFFFFu, s1, off);
        if (lane == 0) g_c1[w] = s1;
        float s2 = 0.f;
        for (int h = lane; h < Hh; h += 32) s2 += Wm2[w * Hh + h] * st[h];
        #pragma unroll
        for (int off = 16; off; off >>= 1) s2 += __shfl_xor_sync(0xFFFFFFFFu, s2, off);
        if (lane == 0) g_bc[w] = s2 + bm2[w];
    }
}

// z' = dinv * (X @ Wfold): one warp per node, float4 loads of the 1KB row.
__global__ void gemv_kernel(const float* __restrict__ x, int n) {
    __shared__ float sW[Dd * Cc];
    for (int i = threadIdx.x; i < Dd * Cc; i += blockDim.x) sW[i] = g_W[i];
    __syncthreads();
    int gw = (blockIdx.x * blockDim.x + threadIdx.x) >> 5;
    int lane = threadIdx.x & 31;
    if (gw >= n) return;
    const float4* xr = (const float4*)x + (size_t)gw * (Dd / 4);
    float a0 = 0.f, a1 = 0.f, a2 = 0.f, a3 = 0.f, a4 = 0.f;
    #pragma unroll
    for (int it = 0; it < 2; ++it) {
        float4 v = xr[it * 32 + lane];
        const float* w = &sW[(it * 32 + lane) * 4 * Cc];
        a0 += v.x * w[0] + v.y * w[5] + v.z * w[10] + v.w * w[15];
        a1 += v.x * w[1] + v.y * w[6] + v.z * w[11] + v.w * w[16];
        a2 += v.x * w[2] + v.y * w[7] + v.z * w[12] + v.w * w[17];
        a3 += v.x * w[3] + v.y * w[8] + v.z * w[13] + v.w * w[18];
        a4 += v.x * w[4] + v.y * w[9] + v.z * w[14] + v.w * w[19];
    }
    #pragma unroll
    for (int off = 16; off; off >>= 1) {
        a0 += __shfl_xor_sync(0xFFFFFFFFu, a0, off);
        a1 += __shfl_xor_sync(0xFFFFFFFFu, a1, off);
        a2 += __shfl_xor_sync(0xFFFFFFFFu, a2, off);
        a3 += __shfl_xor_sync(0xFFFFFFFFu, a3, off);
        a4 += __shfl_xor_sync(0xFFFFFFFFu, a4, off);
    }
    if (lane == 0) {
        float w = g_dinv[gw];
        float* o = &g_bufA[(size_t)gw * Ss];
        o[0] = w * a0; o[1] = w * a1; o[2] = w * a2; o[3] = w * a3; o[4] = w * a4;
    }
}

#define WARP_RED5()                                                        \
    _Pragma("unroll")                                                      \
    for (int off = 16; off; off >>= 1) {                                   \
        a0 += __shfl_xor_sync(0xFFFFFFFFu, a0, off);                       \
        a1 += __shfl_xor_sync(0xFFFFFFFFu, a1, off);                       \
        a2 += __shfl_xor_sync(0xFFFFFFFFu, a2, off);                       \
        a3 += __shfl_xor_sync(0xFFFFFFFFu, a3, off);                       \
        a4 += __shfl_xor_sync(0xFFFFFFFFu, a4, off);                       \
    }

// Pass 1: warp per node gathers bufA over in-edges; fused fin1 -> bufB (q)
__global__ void agg1_kernel(int n) {
    int gw = (blockIdx.x * blockDim.x + threadIdx.x) >> 5;
    int lane = threadIdx.x & 31;
    if (gw >= n) return;
    int start = g_rowstart[gw];
    int m = g_cnt[gw];
    float a0 = 0.f, a1 = 0.f, a2 = 0.f, a3 = 0.f, a4 = 0.f;
    for (int j = lane; j < m; j += 32) {
        int s = __ldg(&g_srcs[start + j]);
        const float* vs = &g_bufA[(size_t)s * Ss];
        float4 v = *(const float4*)vs;
        a0 += v.x; a1 += v.y; a2 += v.z; a3 += v.w; a4 += vs[4];
    }
    WARP_RED5();
    if (lane == 0) {
        float w = g_dinv[gw];
        const float* z = &g_bufA[(size_t)gw * Ss];
        float* q = &g_bufB[(size_t)gw * Ss];
        q[0] = w * (w * (a0 + z[0]) + g_c1[0]);
        q[1] = w * (w * (a1 + z[1]) + g_c1[1]);
        q[2] = w * (w * (a2 + z[2]) + g_c1[2]);
        q[3] = w * (w * (a3 + z[3]) + g_c1[3]);
        q[4] = w * (w * (a4 + z[4]) + g_c1[4]);
    }
}

// Pass 2: gathers bufB; fused fin2 -> out
__global__ void agg2_kernel(float* __restrict__ out, int n) {
    int gw = (blockIdx.x * blockDim.x + threadIdx.x) >> 5;
    int lane = threadIdx.x & 31;
    if (gw >= n) return;
    int start = g_rowstart[gw];
    int m = g_cnt[gw];
    float a0 = 0.f, a1 = 0.f, a2 = 0.f, a3 = 0.f, a4 = 0.f;
    for (int j = lane; j < m; j += 32) {
        int s = __ldg(&g_srcs[start + j]);
        const float* vs = &g_bufB[(size_t)s * Ss];
        float4 v = *(const float4*)vs;
        a0 += v.x; a1 += v.y; a2 += v.z; a3 += v.w; a4 += vs[4];
    }
    WARP_RED5();
    if (lane == 0) {
        float w = g_dinv[gw];
        const float* q = &g_bufB[(size_t)gw * Ss];
        float* o = out + (size_t)gw * Cc;
        o[0] = w * (a0 + q[0]) + g_bc[0];
        o[1] = w * (a1 + q[1]) + g_bc[1];
        o[2] = w * (a2 + q[2]) + g_bc[2];
        o[3] = w * (a3 + q[3]) + g_bc[3];
        o[4] = w * (a4 + q[4]) + g_bc[4];
    }
}

extern "C" void kernel_launch(void* const* d_in, const int* in_sizes, int n_in,
                              void* d_out, int out_size) {
    const float* x   = (const float*)d_in[0];
    const int*   ei  = (const int*)d_in[1];
    const float* W1  = (const float*)d_in[2];
    const float* b1  = (const float*)d_in[3];
    const float* W2  = (const float*)d_in[4];
    const float* b2  = (const float*)d_in[5];
    const float* Wm1 = (const float*)d_in[6];
    const float* bm1 = (const float*)d_in[7];
    const float* Wm2 = (const float*)d_in[8];
    const float* bm2 = (const float*)d_in[9];
    float* out = (float*)d_out;

    int n = in_sizes[0] / Dd;
    int E = in_sizes[1] / 2;
    const int* src = ei;
    const int* dst = ei + E;

    int nb  = (n + 255) / 256;
    int eb  = (E + 255) / 256;
    int gb  = (n * 32 + 255) / 256;   // warp-per-node grids
    int sb  = (n + 1023) / 1024;      // scan blocks (<=128)

    float* pM1  = nullptr; cudaGetSymbolAddress((void**)&pM1,  g_M1);
    float* pWcT = nullptr; cudaGetSymbolAddress((void**)&pWcT, g_WcT);
    float* pW   = nullptr; cudaGetSymbolAddress((void**)&pW,   g_W);

    init_kernel<<<nb, 256>>>(n);
    hist_kernel<<<eb, 256>>>(dst, E);
    scan1_kernel<<<sb, 256>>>(n);
    scan2_kernel<<<1, 128>>>(sb);
    scan3_kernel<<<sb, 256>>>(n);
    scatter_kernel<<<eb, 256>>>(src, dst, E);
    // fold: M1 = Wm1^T Wm2^T ; WcT = W2^T M1 ; Wfold = W1^T WcT
    stage_kernel<<<8, 256>>>(Wm1, Wm2, pM1, Hh, 1);
    stage_kernel<<<16, 256>>>(W2, pM1, pWcT, Dd, 0);
    stage_kernel<<<16, 256>>>(W1, pWcT, pW, Dd, 0);
    bias_kernel<<<1, 256>>>(b1, b2, Wm1, bm1, Wm2, bm2);
    gemv_kernel<<<gb, 256>>>(x, n);
    agg1_kernel<<<gb, 256>>>(n);
    agg2_kernel<<<gb, 256>>>(out, n);
}

// round 5
// speedup vs baseline: 1.2549x; 1.2549x over previous
#include <cuda_runtime.h>

// ---------------------------------------------------------------------------
// GCN(D=256) x2 + MLP head, algebraically folded:
//   out = A( A (X Wfold) + c1*1 ) + bc ,  Wfold = W1^T W2^T Wm1^T Wm2^T [256x5]
// A = D^{-1/2}(Adj+I)D^{-1/2}; dinv factored out of edge kernels.
// R5: revert to R3's RED-atomic edge engine (CSR gather regressed);
//     + stream fork/join (fold+gemv overlap deg+dinv) inside graph capture;
//     + 2 edges/thread with int2 index loads in agg (MLP=2 on row gathers).
// ---------------------------------------------------------------------------

#define Dd 256
#define Hh 128
#define Cc 5
#define Ss 8           // padded row stride (32B rows -> 1 L2 sector)
#define NMAX 100352

__device__ float g_deg[NMAX];        // degree, then dinv in-place
__device__ float g_bufA[NMAX * Ss];  // z' (=dinv*z), then q (=dinv*p)
__device__ float g_bufB[NMAX * Ss];  // edge-sum accumulator (both passes)
__device__ float g_M1[Dd * Cc];      // fold stage-1 intermediate
__device__ float g_WcT[Dd * Cc];     // fold stage-2 intermediate
__device__ float g_W[Dd * Cc];       // folded 256x5 weight
__device__ float g_c1[Cc];
__device__ float g_bc[Cc];

__global__ void init_kernel(int n) {
    int i = blockIdx.x * blockDim.x + threadIdx.x;
    if (i < n) {
        g_deg[i] = 1.0f;  // self-loop contributes 1 to degree
        float4 z = make_float4(0.f, 0.f, 0.f, 0.f);
        ((float4*)g_bufB)[i * 2 + 0] = z;
        ((float4*)g_bufB)[i * 2 + 1] = z;
    }
    if (i < Dd * Cc) { g_M1[i] = 0.f; g_WcT[i] = 0.f; g_W[i] = 0.f; }
}

__global__ void deg_kernel(const int* __restrict__ dst, int E) {
    int t = blockIdx.x * blockDim.x + threadIdx.x;
    int e0 = t * 2;
    if (e0 + 1 < E) {
        int2 d = __ldg((const int2*)(dst + e0));
        atomicAdd(&g_deg[d.x], 1.0f);
        atomicAdd(&g_deg[d.y], 1.0f);
    } else if (e0 < E) {
        atomicAdd(&g_deg[__ldg(dst + e0)], 1.0f);
    }
}

__global__ void dinv_kernel(int n) {
    int i = blockIdx.x * blockDim.x + threadIdx.x;
    if (i < n) g_deg[i] = rsqrtf(g_deg[i]);  // deg >= 1 always
}

// Fold stage: Out[t][c] += sum_{k chunk} A[k*Dd + t] * B[k][c]; bT: B stored [Cc x kdim]
__global__ void stage_kernel(const float* __restrict__ A, const float* __restrict__ B,
                             float* __restrict__ Out, int kdim, int bT) {
    __shared__ float sB[Dd * Cc];
    int tid = threadIdx.x;
    for (int i = tid; i < kdim * Cc; i += blockDim.x) {
        int k = i / Cc, c = i - k * Cc;
        sB[i] = bT ? B[c * kdim + k] : B[i];
    }
    __syncthreads();
    int chunk = kdim / gridDim.x;
    int k0 = blockIdx.x * chunk;
    float acc[Cc] = {};
    for (int k = k0; k < k0 + chunk; ++k) {
        float a = A[k * Dd + tid];
        #pragma unroll
        for (int c = 0; c < Cc; ++c) acc[c] += a * sB[k * Cc + c];
    }
    #pragma unroll
    for (int c = 0; c < Cc; ++c) atomicAdd(&Out[tid * Cc + c], acc[c]);
}

// Bias folds: c1 = b1 @ WcT ; bc = Wm2 (Wm1 b2 + bm1) + bm2
__global__ void bias_kernel(const float* __restrict__ b1, const float* __restrict__ b2,
                            const float* __restrict__ Wm1, const float* __restrict__ bm1,
                            const float* __restrict__ Wm2, const float* __restrict__ bm2) {
    __shared__ float st[Hh];
    int tid = threadIdx.x, w = tid >> 5, lane = tid & 31;  // 8 warps
    for (int i = 0; i < 16; ++i) {
        int h = w * 16 + i;
        float s = 0.f;
        for (int d = lane; d < Dd; d += 32) s += Wm1[h * Dd + d] * b2[d];
        #pragma unroll
        for (int off = 16; off; off >>= 1) s += __shfl_xor_sync(0xFFFFFFFFu, s, off);
        if (lane == 0) st[h] = s + bm1[h];
    }
    __syncthreads();
    if (w < Cc) {
        float s1 = 0.f;
        for (int d = lane; d < Dd; d += 32) s1 += b1[d] * g_WcT[d * Cc + w];
        #pragma unroll
        for (int off = 16; off; off >>= 1) s1 += __shfl_xor_sync(0xFFFFFFFFu, s1, off);
        if (lane == 0) g_c1[w] = s1;
        float s2 = 0.f;
        for (int h = lane; h < Hh; h += 32) s2 += Wm2[w * Hh + h] * st[h];
        #pragma unroll
        for (int off = 16; off; off >>= 1) s2 += __shfl_xor_sync(0xFFFFFFFFu, s2, off);
        if (lane == 0) g_bc[w] = s2 + bm2[w];
    }
}

// z' = dinv * (X @ Wfold): one warp per node, float4 loads of the 1KB row.
__global__ void gemv_kernel(const float* __restrict__ x, int n) {
    __shared__ float sW[Dd * Cc];
    for (int i = threadIdx.x; i < Dd * Cc; i += blockDim.x) sW[i] = g_W[i];
    __syncthreads();
    int gw = (blockIdx.x * blockDim.x + threadIdx.x) >> 5;
    int lane = threadIdx.x & 31;
    if (gw >= n) return;
    const float4* xr = (const float4*)x + (size_t)gw * (Dd / 4);
    float a0 = 0.f, a1 = 0.f, a2 = 0.f, a3 = 0.f, a4 = 0.f;
    #pragma unroll
    for (int it = 0; it < 2; ++it) {
        float4 v = xr[it * 32 + lane];
        const float* w = &sW[(it * 32 + lane) * 4 * Cc];
        a0 += v.x * w[0] + v.y * w[5] + v.z * w[10] + v.w * w[15];
        a1 += v.x * w[1] + v.y * w[6] + v.z * w[11] + v.w * w[16];
        a2 += v.x * w[2] + v.y * w[7] + v.z * w[12] + v.w * w[17];
        a3 += v.x * w[3] + v.y * w[8] + v.z * w[13] + v.w * w[18];
        a4 += v.x * w[4] + v.y * w[9] + v.z * w[14] + v.w * w[19];
    }
    #pragma unroll
    for (int off = 16; off; off >>= 1) {
        a0 += __shfl_xor_sync(0xFFFFFFFFu, a0, off);
        a1 += __shfl_xor_sync(0xFFFFFFFFu, a1, off);
        a2 += __shfl_xor_sync(0xFFFFFFFFu, a2, off);
        a3 += __shfl_xor_sync(0xFFFFFFFFu, a3, off);
        a4 += __shfl_xor_sync(0xFFFFFFFFu, a4, off);
    }
    if (lane == 0) {
        float w = g_deg[gw];  // dinv
        float* o = &g_bufA[(size_t)gw * Ss];
        o[0] = w * a0; o[1] = w * a1; o[2] = w * a2; o[3] = w * a3; o[4] = w * a4;
    }
}

__device__ __forceinline__ void red_row(int d, float4 a, float a4) {
    float* vd = &g_bufB[(size_t)d * Ss];
    unsigned long long gp = __cvta_generic_to_global(vd);
    asm volatile("red.global.add.v4.f32 [%0], {%1, %2, %3, %4};"
                 :: "l"(gp), "f"(a.x), "f"(a.y), "f"(a.z), "f"(a.w) : "memory");
    atomicAdd(vd + 4, a4);
}

// Edge pass: bufB[dst] += bufA[src], 2 edges per thread (MLP=2 on gathers).
__global__ void agg_kernel(const int* __restrict__ src, const int* __restrict__ dst, int E) {
    int t = blockIdx.x * blockDim.x + threadIdx.x;
    int e0 = t * 2;
    if (e0 + 1 < E) {
        int2 s = __ldg((const int2*)(src + e0));
        int2 d = __ldg((const int2*)(dst + e0));
        const float* vs0 = &g_bufA[(size_t)s.x * Ss];
        const float* vs1 = &g_bufA[(size_t)s.y * Ss];
        float4 a = *(const float4*)vs0;
        float4 b = *(const float4*)vs1;
        float a4 = vs0[4];
        float b4 = vs1[4];
        red_row(d.x, a, a4);
        red_row(d.y, b, b4);
    } else if (e0 < E) {
        int s = __ldg(src + e0);
        int d = __ldg(dst + e0);
        const float* vs = &g_bufA[(size_t)s * Ss];
        red_row(d, *(const float4*)vs, vs[4]);
    }
}

// After pass 1: p = dinv*(S1 + z') + c1 ;  q = dinv*p -> bufA; reset bufB.
__global__ void fin1_kernel(int n) {
    int i = blockIdx.x * blockDim.x + threadIdx.x;
    if (i >= n) return;
    float w = g_deg[i];
    #pragma unroll
    for (int c = 0; c < Cc; ++c) {
        float pp = w * (g_bufB[i * Ss + c] + g_bufA[i * Ss + c]) + g_c1[c];
        g_bufA[i * Ss + c] = w * pp;
        g_bufB[i * Ss + c] = 0.f;
    }
}

// After pass 2: out = dinv*(S2 + q) + bc
__global__ void fin2_kernel(float* __restrict__ out, int n) {
    int i = blockIdx.x * blockDim.x + threadIdx.x;
    if (i >= n) return;
    float w = g_deg[i];
    #pragma unroll
    for (int c = 0; c < Cc; ++c) {
        out[i * Cc + c] = w * (g_bufB[i * Ss + c] + g_bufA[i * Ss + c]) + g_bc[c];
    }
}

extern "C" void kernel_launch(void* const* d_in, const int* in_sizes, int n_in,
                              void* d_out, int out_size) {
    const float* x   = (const float*)d_in[0];
    const int*   ei  = (const int*)d_in[1];
    const float* W1  = (const float*)d_in[2];
    const float* b1  = (const float*)d_in[3];
    const float* W2  = (const float*)d_in[4];
    const float* b2  = (const float*)d_in[5];
    const float* Wm1 = (const float*)d_in[6];
    const float* bm1 = (const float*)d_in[7];
    const float* Wm2 = (const float*)d_in[8];
    const float* bm2 = (const float*)d_in[9];
    float* out = (float*)d_out;

    int n = in_sizes[0] / Dd;
    int E = in_sizes[1] / 2;
    const int* src = ei;
    const int* dst = ei + E;

    int nb  = (n + 255) / 256;
    int eb2 = ((E + 1) / 2 + 255) / 256;   // 2 edges/thread
    int gb  = (n * 32 + 255) / 256;        // warp-per-node GEMV

    float* pM1  = nullptr; cudaGetSymbolAddress((void**)&pM1,  g_M1);
    float* pWcT = nullptr; cudaGetSymbolAddress((void**)&pWcT, g_WcT);
    float* pW   = nullptr; cudaGetSymbolAddress((void**)&pW,   g_W);

    // Fresh side stream + events each call (kernel_launch runs only twice:
    // once uncaptured for correctness, once under graph capture). Event-based
    // fork/join is the documented capturable pattern; never destroyed, so no
    // destroy-during-capture hazard.
    cudaStream_t side;
    cudaStreamCreateWithFlags(&side, cudaStreamNonBlocking);
    cudaEvent_t eInit, eDinv, eSide;
    cudaEventCreateWithFlags(&eInit, cudaEventDisableTiming);
    cudaEventCreateWithFlags(&eDinv, cudaEventDisableTiming);
    cudaEventCreateWithFlags(&eSide, cudaEventDisableTiming);

    // main: init -> deg -> dinv
    init_kernel<<<nb, 256>>>(n);
    cudaEventRecord(eInit, 0);
    deg_kernel<<<eb2, 256>>>(dst, E);
    dinv_kernel<<<nb, 256>>>(n);
    cudaEventRecord(eDinv, 0);

    // side: fold chain + bias (independent of deg), then gemv (needs dinv too)
    cudaStreamWaitEvent(side, eInit, 0);
    stage_kernel<<<8, 256, 0, side>>>(Wm1, Wm2, pM1, Hh, 1);
    stage_kernel<<<16, 256, 0, side>>>(W2, pM1, pWcT, Dd, 0);
    stage_kernel<<<16, 256, 0, side>>>(W1, pWcT, pW, Dd, 0);
    bias_kernel<<<1, 256, 0, side>>>(b1, b2, Wm1, bm1, Wm2, bm2);
    cudaStreamWaitEvent(side, eDinv, 0);
    gemv_kernel<<<gb, 256, 0, side>>>(x, n);
    cudaEventRecord(eSide, side);

    // main: join, then edge passes
    cudaStreamWaitEvent(0, eSide, 0);
    agg_kernel<<<eb2, 256>>>(src, dst, E);   // pass 1
    fin1_kernel<<<nb, 256>>>(n);
    agg_kernel<<<eb2, 256>>>(src, dst, E);   // pass 2
    fin2_kernel<<<nb, 256>>>(out, n);
}